// round 2
// baseline (speedup 1.0000x reference)
#include <cuda_runtime.h>
#include <math.h>
#include <stdint.h>
#include <stddef.h>

// ---- problem constants ----
#define HD  256      // HIDDEN_DIM
#define ZD  64       // Z_DIM
#define BB  8        // batch
#define SL  2048     // SRC_LEN
#define QT  16       // queries per block in k_attn
#define KC  256      // key chunk in k_attn
#define CAP 128      // per-row nonzero-attn list capacity
#define SKIP_T (-88.0f)

// ---- device scratch (no allocation allowed) ----
__device__ float g_venc[BB][HD];     // v_enc per batch
__device__ float g_qenc[BB][HD];     // q_enc per batch (only used to form u)
__device__ float g_u[BB][ZD];        // u_b = Wk_z q_enc
__device__ float g_zsum[BB][ZD];     // sum_k z[b,k,:]
__device__ float g_M[ZD][ZD];        // Wq_z Wk_z^T
__device__ float g_wT[BB * ZD * SL]; // w transposed: [b][d][key], w = (M z_k)/16
__device__ float g_c[BB][SL];        // c_k = (u_b . z_k)/16

// =================== kernel 1: per-batch constants + M =====================
// grid = 12 (8 batch blocks + 4 M-tile blocks), 256 threads
__global__ void k_prep(const float* __restrict__ ehs,
                       const float* __restrict__ z,
                       const float* __restrict__ wq,
                       const float* __restrict__ wk,
                       const float* __restrict__ wv) {
    int t = threadIdx.x;
    if (blockIdx.x < BB) {
        int b = blockIdx.x;
        __shared__ float enc[HD];
        __shared__ float qe[HD];
        __shared__ float zs[4][ZD];
        // enc = sum over 2 directions
        enc[t] = ehs[b * HD + t] + ehs[BB * HD + b * HD + t];
        __syncthreads();
        float aq = 0.f, av = 0.f;
        for (int d = 0; d < HD; d++) {
            float ev = enc[d];
            aq += ev * wq[d * HD + t];
            av += ev * wv[d * HD + t];
        }
        qe[t] = aq;
        g_qenc[b][t] = aq;
        g_venc[b][t] = av;
        __syncthreads();
        if (t < ZD) {
            float au = 0.f;
            for (int h = 0; h < HD; h++) au += qe[h] * wk[(HD + t) * HD + h];
            g_u[b][t] = au;
        }
        // zsum[b][e]
        int e = t & 63, part = t >> 6;
        const float* zp = z + (size_t)b * SL * ZD;
        float s = 0.f;
        for (int k = part * 512; k < part * 512 + 512; k++)
            s += zp[(size_t)k * ZD + e];
        zs[part][e] = s;
        __syncthreads();
        if (t < ZD) g_zsum[b][t] = zs[0][t] + zs[1][t] + zs[2][t] + zs[3][t];
    } else {
        // M[d][e] = sum_h Wq_z[d,h] * Wk_z[e,h]
        int i = blockIdx.x - BB;    // tile of 16 d-rows
        int e = t & 63, dl = t >> 6;
        for (int j = 0; j < 4; j++) {
            int d = i * 16 + dl * 4 + j;
            const float* qrow = wq + (size_t)(HD + d) * HD;
            const float* krow = wk + (size_t)(HD + e) * HD;
            float acc = 0.f;
            for (int h = 0; h < HD; h++) acc += qrow[h] * krow[h];
            g_M[d][e] = acc;
        }
    }
}

// ===== kernel 2: wT[b,d,k] = (M z_k)[d]/16, c[b,k] = (u_b.z_k)/16 ==========
// grid = 128 blocks * 128 threads (1 key/thread)
__global__ void k_wc(const float* __restrict__ z) {
    __shared__ float Ms[ZD][ZD];
    __shared__ float us[ZD];
    int t = threadIdx.x;
    int b = blockIdx.x >> 4;
    int k0 = (blockIdx.x & 15) * 128;
    for (int i = t; i < ZD * ZD / 4; i += 128)
        ((float4*)Ms)[i] = ((const float4*)g_M)[i];
    if (t < ZD) us[t] = g_u[b][t];
    __syncthreads();

    int key = k0 + t;
    const float4* zp4 = (const float4*)(z + ((size_t)b * SL + key) * ZD);
    float zr[ZD];
#pragma unroll
    for (int i = 0; i < ZD / 4; i++) {
        float4 v = zp4[i];
        zr[4 * i + 0] = v.x; zr[4 * i + 1] = v.y;
        zr[4 * i + 2] = v.z; zr[4 * i + 3] = v.w;
    }
    const float inv_t = 0.0625f;  // 1/sqrt(HD)
    float cacc = 0.f;
#pragma unroll
    for (int e = 0; e < ZD; e++) cacc += zr[e] * us[e];
    g_c[b][key] = cacc * inv_t;

    float* wt = g_wT + (size_t)b * ZD * SL;
#pragma unroll
    for (int d4 = 0; d4 < ZD / 4; d4++) {
        float a0 = 0.f, a1 = 0.f, a2 = 0.f, a3 = 0.f;
#pragma unroll
        for (int e4 = 0; e4 < ZD / 4; e4++) {
            float4 m0 = ((const float4*)&Ms[4 * d4 + 0][0])[e4];
            float4 m1 = ((const float4*)&Ms[4 * d4 + 1][0])[e4];
            float4 m2 = ((const float4*)&Ms[4 * d4 + 2][0])[e4];
            float4 m3 = ((const float4*)&Ms[4 * d4 + 3][0])[e4];
            float z0 = zr[4 * e4 + 0], z1 = zr[4 * e4 + 1];
            float z2 = zr[4 * e4 + 2], z3 = zr[4 * e4 + 3];
            a0 += m0.x * z0 + m0.y * z1 + m0.z * z2 + m0.w * z3;
            a1 += m1.x * z0 + m1.y * z1 + m1.z * z2 + m1.w * z3;
            a2 += m2.x * z0 + m2.y * z1 + m2.z * z2 + m2.w * z3;
            a3 += m3.x * z0 + m3.y * z1 + m3.z * z2 + m3.w * z3;
        }
        wt[(size_t)(4 * d4 + 0) * SL + key] = a0 * inv_t;
        wt[(size_t)(4 * d4 + 1) * SL + key] = a1 * inv_t;
        wt[(size_t)(4 * d4 + 2) * SL + key] = a2 * inv_t;
        wt[(size_t)(4 * d4 + 3) * SL + key] = a3 * inv_t;
    }
}

// =================== kernel 3: scores + softmax + output ===================
struct __align__(16) AttnSmem {
    float sc[QT][SL];        // 131072 B: score tile -> then exp values
    float w[ZD][KC];         //  65536 B: w chunk, d-major
    float zq[QT][ZD];        //   4096 B
    float yT[ZD][QT];        //   4096 B: y transposed [e][q]
    float pv[QT][CAP];       //   8192 B: nonzero exp values
    int   kv[QT][CAP];       //   8192 B: nonzero key indices
    int   cnt[QT];
    float invZ_s[QT];
    int   mskd[QT];
};                            // total 221,632 B < 227 KB

__global__ void __launch_bounds__(256, 1)
k_attn(const float* __restrict__ z, const float* __restrict__ wv,
       const int* __restrict__ mask, float* __restrict__ outp,
       float* __restrict__ attnp) {
    extern __shared__ char smraw[];
    AttnSmem& s = *reinterpret_cast<AttnSmem*>(smraw);
    int t = threadIdx.x;
    int b = blockIdx.x >> 7;           // 128 q-tiles per batch
    int q0 = (blockIdx.x & 127) * QT;

    // load z_q tile [QT][ZD]
    {
        int qr = t >> 4, f4 = t & 15;
        float4 v = *((const float4*)(z + ((size_t)b * SL + q0 + qr) * ZD) + f4);
        *((float4*)&s.zq[qr][0] + f4) = v;
    }

    int kq = t & 63, qg = t >> 6;
    int kk = kq * 4;
    const float* gwT = g_wT + (size_t)b * ZD * SL;

    // ---- score GEMM: sc[q][k] = zq . w_k + c_k ----
    for (int ch = 0; ch < SL / KC; ch++) {
        int k0 = ch * KC;
        __syncthreads();   // protect previous chunk's w reads / zq store
        // load w chunk [64][256] (d-major rows, contiguous from gwT)
#pragma unroll
        for (int i = 0; i < 16; i++) {
            int idx = t + i * 256;
            int e = idx >> 6, f4 = idx & 63;
            float4 v = *((const float4*)(gwT + (size_t)e * SL + k0) + f4);
            *((float4*)&s.w[e][0] + f4) = v;
        }
        __syncthreads();

        float4 cv = *((const float4*)&g_c[b][k0 + kk]);
        float acc[4][4];
#pragma unroll
        for (int i = 0; i < 4; i++) {
            acc[i][0] = cv.x; acc[i][1] = cv.y; acc[i][2] = cv.z; acc[i][3] = cv.w;
        }
#pragma unroll
        for (int e4 = 0; e4 < 16; e4++) {
            const int e = e4 * 4;
            float av[4][4], bv[4][4];
#pragma unroll
            for (int i = 0; i < 4; i++) {
                float4 a = *(const float4*)&s.zq[4 * qg + i][e];
                av[i][0] = a.x; av[i][1] = a.y; av[i][2] = a.z; av[i][3] = a.w;
            }
#pragma unroll
            for (int l = 0; l < 4; l++) {
                float4 w4 = *(const float4*)&s.w[e + l][kk];
                bv[l][0] = w4.x; bv[l][1] = w4.y; bv[l][2] = w4.z; bv[l][3] = w4.w;
            }
#pragma unroll
            for (int i = 0; i < 4; i++)
#pragma unroll
                for (int l = 0; l < 4; l++)
#pragma unroll
                    for (int j = 0; j < 4; j++)
                        acc[i][j] += av[i][l] * bv[l][j];
        }
#pragma unroll
        for (int i = 0; i < 4; i++)
            *((float4*)&s.sc[4 * qg + i][k0 + kk]) =
                make_float4(acc[i][0], acc[i][1], acc[i][2], acc[i][3]);
    }
    __syncthreads();

    // ---- per-row softmax (warp w owns rows 2w, 2w+1) ----
    int w_id = t >> 5, lane = t & 31;
    const float* zb = z + (size_t)b * SL * ZD;

    for (int rr = 0; rr < 2; rr++) {
        int r = w_id * 2 + rr;
        int msk = mask[b * SL + q0 + r];
        if (lane == 0) { s.mskd[r] = msk; s.cnt[r] = 0; }
        __syncwarp();

        float iz = 0.f;
        if (msk != 0) {
            const float4* row4 = (const float4*)&s.sc[r][0];
            float4* row4w = (float4*)&s.sc[r][0];
            // row max
            float mx = -3.4e38f;
#pragma unroll
            for (int i = 0; i < 16; i++) {
                float4 v = row4[i * 32 + lane];
                mx = fmaxf(mx, fmaxf(fmaxf(v.x, v.y), fmaxf(v.z, v.w)));
            }
#pragma unroll
            for (int o = 16; o; o >>= 1) mx = fmaxf(mx, __shfl_xor_sync(~0u, mx, o));
            // exp + Z + sparse list (window-voted skip)
            float Zp = 0.f;
            for (int i = 0; i < 16; i++) {
                int idx = i * 32 + lane;
                float4 v = row4[idx];
                float d0 = v.x - mx, d1 = v.y - mx, d2 = v.z - mx, d3 = v.w - mx;
                float dm = fmaxf(fmaxf(d0, d1), fmaxf(d2, d3));
                unsigned bal = __ballot_sync(~0u, dm >= SKIP_T);
                if (bal == 0) { row4w[idx] = make_float4(0.f, 0.f, 0.f, 0.f); continue; }
                float p0 = __expf(d0), p1 = __expf(d1);
                float p2 = __expf(d2), p3 = __expf(d3);
                row4w[idx] = make_float4(p0, p1, p2, p3);
                Zp += (p0 + p1) + (p2 + p3);
                int kb = idx * 4;
                if (p0 > 0.f) { int p = atomicAdd(&s.cnt[r], 1); if (p < CAP) { s.kv[r][p] = kb + 0; s.pv[r][p] = p0; } }
                if (p1 > 0.f) { int p = atomicAdd(&s.cnt[r], 1); if (p < CAP) { s.kv[r][p] = kb + 1; s.pv[r][p] = p1; } }
                if (p2 > 0.f) { int p = atomicAdd(&s.cnt[r], 1); if (p < CAP) { s.kv[r][p] = kb + 2; s.pv[r][p] = p2; } }
                if (p3 > 0.f) { int p = atomicAdd(&s.cnt[r], 1); if (p < CAP) { s.kv[r][p] = kb + 3; s.pv[r][p] = p3; } }
            }
#pragma unroll
            for (int o = 16; o; o >>= 1) Zp += __shfl_xor_sync(~0u, Zp, o);
            iz = 1.0f / Zp;
            if (lane == 0) s.invZ_s[r] = iz;
        }
        __syncwarp();

        // attn write + y accumulation
        float y0 = 0.f, y1 = 0.f;
        if (msk == 0) {
            if (attnp) {
                const float u = 1.0f / 2048.0f;
                float4 u4 = make_float4(u, u, u, u);
                float4* ap = (float4*)(attnp + (size_t)(b * SL + q0 + r) * SL);
#pragma unroll
                for (int i = 0; i < 16; i++) ap[i * 32 + lane] = u4;
            }
            y0 = g_zsum[b][lane] * (1.0f / 2048.0f);
            y1 = g_zsum[b][lane + 32] * (1.0f / 2048.0f);
        } else {
            if (attnp) {
                const float4* row4 = (const float4*)&s.sc[r][0];
                float4* ap = (float4*)(attnp + (size_t)(b * SL + q0 + r) * SL);
#pragma unroll
                for (int i = 0; i < 16; i++) {
                    float4 p = row4[i * 32 + lane];
                    ap[i * 32 + lane] = make_float4(p.x * iz, p.y * iz, p.z * iz, p.w * iz);
                }
            }
            int cnt = s.cnt[r];
            if (cnt <= CAP) {
                for (int i = 0; i < cnt; i++) {
                    float a = s.pv[r][i] * iz;
                    int k = s.kv[r][i];
                    y0 += a * zb[(size_t)k * ZD + lane];
                    y1 += a * zb[(size_t)k * ZD + lane + 32];
                }
            } else {  // extremely rare dense fallback
                for (int k = 0; k < SL; k++) {
                    float p = s.sc[r][k];
                    if (p != 0.f) {
                        float a = p * iz;
                        y0 += a * zb[(size_t)k * ZD + lane];
                        y1 += a * zb[(size_t)k * ZD + lane + 32];
                    }
                }
            }
        }
        s.yT[lane][r] = y0;
        s.yT[lane + 32][r] = y1;
    }
    __syncthreads();

    // ---- output epilogue: out[q][h] = v_enc[h] + sum_e y[q][e] Wv_z[e][h] ----
    if (outp) {
        float acc[QT];
        float ve = g_venc[b][t];
#pragma unroll
        for (int q = 0; q < QT; q++) acc[q] = ve;
#pragma unroll 4
        for (int e = 0; e < ZD; e++) {
            float wvv = wv[(size_t)(HD + e) * HD + t];
            const float4* yr = (const float4*)&s.yT[e][0];
            float4 ya = yr[0], yb = yr[1], yc = yr[2], yd = yr[3];
            acc[0]  += ya.x * wvv; acc[1]  += ya.y * wvv;
            acc[2]  += ya.z * wvv; acc[3]  += ya.w * wvv;
            acc[4]  += yb.x * wvv; acc[5]  += yb.y * wvv;
            acc[6]  += yb.z * wvv; acc[7]  += yb.w * wvv;
            acc[8]  += yc.x * wvv; acc[9]  += yc.y * wvv;
            acc[10] += yc.z * wvv; acc[11] += yc.w * wvv;
            acc[12] += yd.x * wvv; acc[13] += yd.y * wvv;
            acc[14] += yd.z * wvv; acc[15] += yd.w * wvv;
        }
#pragma unroll
        for (int q = 0; q < QT; q++)
            outp[((size_t)b * SL + q0 + q) * HD + t] = acc[q];
    }
}

// ============================== launch =====================================
extern "C" void kernel_launch(void* const* d_in, const int* in_sizes, int n_in,
                              void* d_out, int out_size) {
    const float* ehs  = (const float*)d_in[0];
    // d_in[1] = decoder_hidden_state (unused by reference)
    const float* z    = (const float*)d_in[2];
    const int*   mask = (const int*)d_in[3];
    const float* wq   = (const float*)d_in[4];
    const float* wk   = (const float*)d_in[5];
    const float* wv   = (const float*)d_in[6];

    const long OUT_N = (long)BB * SL * HD;   //  4,194,304
    const long ATT_N = (long)BB * SL * SL;   // 33,554,432
    float* o = (float*)d_out;
    float* outp = nullptr;
    float* attnp = nullptr;
    if ((long)out_size >= OUT_N + ATT_N) { outp = o; attnp = o + OUT_N; }
    else if ((long)out_size == ATT_N)    { attnp = o; }
    else                                 { outp = o; }

    cudaFuncSetAttribute(k_attn, cudaFuncAttributeMaxDynamicSharedMemorySize,
                         (int)sizeof(AttnSmem));

    k_prep<<<BB + 4, 256>>>(ehs, z, wq, wk, wv);
    k_wc<<<128, 128>>>(z);
    k_attn<<<BB * (SL / QT), 256, sizeof(AttnSmem)>>>(z, wv, mask, outp, attnp);
}